// round 5
// baseline (speedup 1.0000x reference)
#include <cuda_runtime.h>

// PGJANET recurrent scan: B=256, T=2048, H=64, O=2.
// 128 blocks x 256 threads, 2 batch elements per block.
// Phase 1: all threads compute packed-f32x2 partial dots for a/p1/p2/f_h/g_h
//   (slice s of h, both elems), partials stored as packed u64.
// u-finalize on warps 0-3 || y-output on warps 6-7.
// h-finalize FUSED with the f/g u-half dot on warps 4-7 (full u rows in regs).
// 3 __syncthreads per step. All dot inputs read as ulonglong2 (native f32x2
// register pairs from LDS.128 - no packing MOVs).

#define TB 2048
typedef unsigned long long u64;

__device__ __forceinline__ u64 ffma2(u64 a, u64 b, u64 c) {
    u64 d; asm("fma.rn.f32x2 %0, %1, %2, %3;" : "=l"(d) : "l"(a), "l"(b), "l"(c)); return d;
}
__device__ __forceinline__ u64 fadd2(u64 a, u64 b) {
    u64 d; asm("add.rn.f32x2 %0, %1, %2;" : "=l"(d) : "l"(a), "l"(b)); return d;
}
__device__ __forceinline__ float hadd2(u64 v) {
    float lo, hi; asm("mov.b64 {%0,%1}, %2;" : "=f"(lo), "=f"(hi) : "l"(v)); return lo + hi;
}
__device__ __forceinline__ u64 pk2(float lo, float hi) {
    u64 r; asm("mov.b64 %0, {%1,%2};" : "=l"(r) : "f"(lo), "f"(hi)); return r;
}
__device__ __forceinline__ float sigf(float v) {
    return __fdividef(1.f, 1.f + __expf(-v));
}
__device__ __forceinline__ float tanhfast(float v) {
    return fmaf(2.f, sigf(2.f * v), -1.f);
}

__global__ void __launch_bounds__(256, 1)
pgjanet_kernel(const float* __restrict__ x,
               const float* __restrict__ h0,
               const float* __restrict__ Wa,  const float* __restrict__ ba,
               const float* __restrict__ Wp1, const float* __restrict__ bp1,
               const float* __restrict__ Wp2, const float* __restrict__ bp2,
               const float* __restrict__ Wf,  const float* __restrict__ bf,
               const float* __restrict__ Wg,  const float* __restrict__ bg,
               const float* __restrict__ Wo,  const float* __restrict__ bo,
               float* __restrict__ out)
{
    __shared__ __align__(16) float2 xb[2][TB];        // 32 KB
    __shared__ __align__(16) float hbuf[2][64];
    __shared__ __align__(16) float ubuf[2][64];
    __shared__ __align__(16) u64 part[2][5][4][64];   // packed partials, 20 KB

    const int tid  = threadIdx.x;
    const int lane = tid & 31;
    const int wid  = tid >> 5;
    const int j    = tid & 63;      // hidden unit
    const int s    = tid >> 6;      // k-slice 0..3
    const int b0   = blockIdx.x * 2;

    // ---- phase-1 weights: slice s, packed k-pairs (80 floats = 40 u64) ----
    u64 wa[8], wp1[8], wp2[8], wfh[8], wgh[8];
    {
        const float* A = Wa  + j * 65 + s * 16;
        const float* P = Wp1 + j * 65 + s * 16;
        const float* Q = Wp2 + j * 65 + s * 16;
        const float* F = Wf  + j * 128 + s * 16;
        const float* G = Wg  + j * 128 + s * 16;
        #pragma unroll
        for (int i = 0; i < 8; i++) {
            wa[i]  = pk2(A[2*i], A[2*i+1]);
            wp1[i] = pk2(P[2*i], P[2*i+1]);
            wp2[i] = pk2(Q[2*i], Q[2*i+1]);
            wfh[i] = pk2(F[2*i], F[2*i+1]);
            wgh[i] = pk2(G[2*i], G[2*i+1]);
        }
    }

    // ---- u-finalize constants (warps 0-3: (e = tid>>6, j)) ----
    float walast = 0.f, w1last = 0.f, w2last = 0.f, ba_r = 0.f, b1_r = 0.f, b2_r = 0.f;
    if (tid < 128) {
        walast = Wa [j * 65 + 64]; ba_r = ba [j];
        w1last = Wp1[j * 65 + 64]; b1_r = bp1[j];
        w2last = Wp2[j * 65 + 64]; b2_r = bp2[j];
    }

    // ---- h-finalize: full u-half rows of Wf/Wg (warps 4-7: (e=(tid>>6)&1, j)) ----
    u64 wfu[32], wgu[32];
    float bf_r = 0.f, bg_r = 0.f;
    if (tid >= 128) {
        const float* F = Wf + j * 128 + 64;
        const float* G = Wg + j * 128 + 64;
        #pragma unroll
        for (int i = 0; i < 32; i++) {
            wfu[i] = pk2(F[2*i], F[2*i+1]);
            wgu[i] = pk2(G[2*i], G[2*i+1]);
        }
        bf_r = bf[j]; bg_r = bg[j];
    }

    // ---- y-output constants (warps 6,7 -> elem 0,1) ----
    float woA0 = 0.f, woB0 = 0.f, woA1 = 0.f, woB1 = 0.f, bo0 = 0.f, bo1 = 0.f;
    if (wid >= 6) {
        woA0 = Wo[lane];      woB0 = Wo[lane + 32];
        woA1 = Wo[64 + lane]; woB1 = Wo[96 + lane];
        bo0 = bo[0]; bo1 = bo[1];
    }

    // ---- preload x + h0 ----
    {
        const float2* xg0 = (const float2*)x + (size_t)b0 * TB;
        const float2* xg1 = (const float2*)x + (size_t)(b0 + 1) * TB;
        for (int i = tid; i < TB; i += 256) { xb[0][i] = xg0[i]; xb[1][i] = xg1[i]; }
    }
    if (tid < 128) hbuf[tid >> 6][j] = h0[(size_t)(b0 + (tid >> 6)) * 64 + j];
    __syncthreads();

    #pragma unroll 1
    for (int t = 0; t < TB; t++) {
        // ==== phase 1: packed partial dots, 5 gates x 2 elems, slice s ====
        {
            const ulonglong2* h0p = (const ulonglong2*)&hbuf[0][s * 16];
            const ulonglong2* h1p = (const ulonglong2*)&hbuf[1][s * 16];
            u64 aA0 = 0, aP0 = 0, aQ0 = 0, aF0 = 0, aG0 = 0;
            u64 aA1 = 0, aP1 = 0, aQ1 = 0, aF1 = 0, aG1 = 0;
            #pragma unroll
            for (int r = 0; r < 4; r++) {
                ulonglong2 v0 = h0p[r], v1 = h1p[r];
                aA0 = ffma2(wa [2*r], v0.x, aA0); aA0 = ffma2(wa [2*r+1], v0.y, aA0);
                aP0 = ffma2(wp1[2*r], v0.x, aP0); aP0 = ffma2(wp1[2*r+1], v0.y, aP0);
                aQ0 = ffma2(wp2[2*r], v0.x, aQ0); aQ0 = ffma2(wp2[2*r+1], v0.y, aQ0);
                aF0 = ffma2(wfh[2*r], v0.x, aF0); aF0 = ffma2(wfh[2*r+1], v0.y, aF0);
                aG0 = ffma2(wgh[2*r], v0.x, aG0); aG0 = ffma2(wgh[2*r+1], v0.y, aG0);
                aA1 = ffma2(wa [2*r], v1.x, aA1); aA1 = ffma2(wa [2*r+1], v1.y, aA1);
                aP1 = ffma2(wp1[2*r], v1.x, aP1); aP1 = ffma2(wp1[2*r+1], v1.y, aP1);
                aQ1 = ffma2(wp2[2*r], v1.x, aQ1); aQ1 = ffma2(wp2[2*r+1], v1.y, aQ1);
                aF1 = ffma2(wfh[2*r], v1.x, aF1); aF1 = ffma2(wfh[2*r+1], v1.y, aF1);
                aG1 = ffma2(wgh[2*r], v1.x, aG1); aG1 = ffma2(wgh[2*r+1], v1.y, aG1);
            }
            part[0][0][s][j] = aA0;  part[1][0][s][j] = aA1;
            part[0][1][s][j] = aP0;  part[1][1][s][j] = aP1;
            part[0][2][s][j] = aQ0;  part[1][2][s][j] = aQ1;
            part[0][3][s][j] = aF0;  part[1][3][s][j] = aF1;
            part[0][4][s][j] = aG0;  part[1][4][s][j] = aG1;
        }
        __syncthreads();   // #1: partials + last h-readers done

        if (tid < 128) {
            // ==== u-finalize (warps 0-3) ====
            const int e = tid >> 6;
            float2 xv = xb[e][t];
            float s2 = fmaf(xv.x, xv.x, xv.y * xv.y);
            float ri = rsqrtf(s2);
            float amp, ct, st;
            if (s2 > 0.f) { amp = s2 * ri; ct = xv.x * ri; st = xv.y * ri; }
            else          { amp = 0.f;     ct = 1.f;       st = 0.f; }
            u64 sa2 = fadd2(fadd2(part[e][0][0][j], part[e][0][1][j]),
                            fadd2(part[e][0][2][j], part[e][0][3][j]));
            u64 sp2 = fadd2(fadd2(part[e][1][0][j], part[e][1][1][j]),
                            fadd2(part[e][1][2][j], part[e][1][3][j]));
            u64 sq2 = fadd2(fadd2(part[e][2][0][j], part[e][2][1][j]),
                            fadd2(part[e][2][2][j], part[e][2][3][j]));
            float av  = tanhfast(fmaf(amp, walast, hadd2(sa2) + ba_r));
            float p1v = tanhfast(fmaf(ct,  w1last, hadd2(sp2) + b1_r));
            float p2v = tanhfast(fmaf(st,  w2last, hadd2(sq2) + b2_r));
            ubuf[e][j] = (av - av * av) * (p1v - p1v * p1v) * (p2v - p2v * p2v);
        } else if (wid >= 6 && t > 0) {
            // ==== y output for step t-1 (warps 6-7, overlapped) ====
            const int e = wid - 6;
            float ha = hbuf[e][lane], hb = hbuf[e][lane + 32];
            float y0 = ha * woA0 + hb * woB0;
            float y1 = ha * woA1 + hb * woB1;
            #pragma unroll
            for (int off = 16; off; off >>= 1) {
                y0 += __shfl_xor_sync(~0u, y0, off);
                y1 += __shfl_xor_sync(~0u, y1, off);
            }
            if (lane == 0)
                ((float2*)out)[(size_t)(b0 + e) * TB + (t - 1)] =
                    make_float2(y0 + bo0, y1 + bo1);
        }
        __syncthreads();   // #2: ubuf ready

        if (tid >= 128) {
            // ==== fused u-half dot + h-finalize (warps 4-7) ====
            const int e = (tid >> 6) & 1;
            const ulonglong2* up = (const ulonglong2*)&ubuf[e][0];   // 16 x 16B
            u64 fa = 0, fb = 0, ga = 0, gb = 0;
            #pragma unroll
            for (int r = 0; r < 16; r++) {
                ulonglong2 v = up[r];
                fa = ffma2(wfu[2*r], v.x, fa); fb = ffma2(wfu[2*r+1], v.y, fb);
                ga = ffma2(wgu[2*r], v.x, ga); gb = ffma2(wgu[2*r+1], v.y, gb);
            }
            u64 sf2 = fadd2(fadd2(part[e][3][0][j], part[e][3][1][j]),
                            fadd2(part[e][3][2][j], part[e][3][3][j]));
            u64 sg2 = fadd2(fadd2(part[e][4][0][j], part[e][4][1][j]),
                            fadd2(part[e][4][2][j], part[e][4][3][j]));
            sf2 = fadd2(sf2, fadd2(fa, fb));
            sg2 = fadd2(sg2, fadd2(ga, gb));
            float f = sigf(hadd2(sf2) + bf_r);
            float g = tanhfast(hadd2(sg2) + bg_r);
            float hold = hbuf[e][j];
            hbuf[e][j] = fmaf(f, hold - g, g);   // f*h + (1-f)*g
        }
        __syncthreads();   // #3: hbuf ready for next step
    }

    // ---- epilogue: y for t = TB-1 ----
    if (wid >= 6) {
        const int e = wid - 6;
        float ha = hbuf[e][lane], hb = hbuf[e][lane + 32];
        float y0 = ha * woA0 + hb * woB0;
        float y1 = ha * woA1 + hb * woB1;
        #pragma unroll
        for (int off = 16; off; off >>= 1) {
            y0 += __shfl_xor_sync(~0u, y0, off);
            y1 += __shfl_xor_sync(~0u, y1, off);
        }
        if (lane == 0)
            ((float2*)out)[(size_t)(b0 + e) * TB + (TB - 1)] =
                make_float2(y0 + bo0, y1 + bo1);
    }
}

extern "C" void kernel_launch(void* const* d_in, const int* in_sizes, int n_in,
                              void* d_out, int out_size)
{
    const float* x   = (const float*)d_in[0];
    const float* h0  = (const float*)d_in[1];
    const float* Wa  = (const float*)d_in[2];
    const float* ba  = (const float*)d_in[3];
    const float* Wp1 = (const float*)d_in[4];
    const float* bp1 = (const float*)d_in[5];
    const float* Wp2 = (const float*)d_in[6];
    const float* bp2 = (const float*)d_in[7];
    const float* Wf  = (const float*)d_in[8];
    const float* bf  = (const float*)d_in[9];
    const float* Wg  = (const float*)d_in[10];
    const float* bg  = (const float*)d_in[11];
    const float* Wo  = (const float*)d_in[12];
    const float* bo  = (const float*)d_in[13];
    float* out = (float*)d_out;

    pgjanet_kernel<<<128, 256>>>(x, h0, Wa, ba, Wp1, bp1, Wp2, bp2,
                                 Wf, bf, Wg, bg, Wo, bo, out);
}

// round 7
// speedup vs baseline: 1.1169x; 1.1169x over previous
#include <cuda_runtime.h>

// PGJANET recurrent scan: B=256, T=2048, H=64, O=2.
// 128 blocks x 256 threads, 2 batch elements per block. R4 structure
// (4 barriers/step, smem partial reduction, no weight fusion), all dot
// products via fma.rn.f32x2 (FFMA2, full-rate rt=1 vs scalar FFMA rt=2).
// Partials stored packed (u64). u-finalize warps 0-3 || y-output warps 6-7;
// h-finalize warps 4-7.
// R6 bug fixed: phase-2 slice is 16 floats = 8 u64 (was 4) and 4 ulonglong2
// loop iterations (was 2).

#define TB 2048
typedef unsigned long long u64;

__device__ __forceinline__ u64 ffma2(u64 a, u64 b, u64 c) {
    u64 d; asm("fma.rn.f32x2 %0, %1, %2, %3;" : "=l"(d) : "l"(a), "l"(b), "l"(c)); return d;
}
__device__ __forceinline__ u64 fadd2(u64 a, u64 b) {
    u64 d; asm("add.rn.f32x2 %0, %1, %2;" : "=l"(d) : "l"(a), "l"(b)); return d;
}
__device__ __forceinline__ float hadd2(u64 v) {
    float lo, hi; asm("mov.b64 {%0,%1}, %2;" : "=f"(lo), "=f"(hi) : "l"(v)); return lo + hi;
}
__device__ __forceinline__ u64 pk2(float lo, float hi) {
    u64 r; asm("mov.b64 %0, {%1,%2};" : "=l"(r) : "f"(lo), "f"(hi)); return r;
}
__device__ __forceinline__ float sigf(float v) {
    return __fdividef(1.f, 1.f + __expf(-v));
}
__device__ __forceinline__ float tanhfast(float v) {
    return fmaf(2.f, sigf(2.f * v), -1.f);
}

__global__ void __launch_bounds__(256, 1)
pgjanet_kernel(const float* __restrict__ x,
               const float* __restrict__ h0,
               const float* __restrict__ Wa,  const float* __restrict__ ba,
               const float* __restrict__ Wp1, const float* __restrict__ bp1,
               const float* __restrict__ Wp2, const float* __restrict__ bp2,
               const float* __restrict__ Wf,  const float* __restrict__ bf,
               const float* __restrict__ Wg,  const float* __restrict__ bg,
               const float* __restrict__ Wo,  const float* __restrict__ bo,
               float* __restrict__ out)
{
    __shared__ __align__(16) float2 xb[2][TB];        // 32 KB
    __shared__ __align__(16) float hbuf[2][64];
    __shared__ __align__(16) float ubuf[2][64];
    __shared__ __align__(16) u64 part[2][5][4][64];   // packed partials, 20 KB

    const int tid  = threadIdx.x;
    const int lane = tid & 31;
    const int wid  = tid >> 5;
    const int j    = tid & 63;      // hidden unit
    const int s    = tid >> 6;      // k-slice 0..3
    const int b0   = blockIdx.x * 2;

    // ---- phase-1 weights: slice s of h, packed k-pairs (40 u64 = 80 regs) ----
    u64 wa[8], wp1[8], wp2[8], wfh[8], wgh[8];
    {
        const float* A = Wa  + j * 65 + s * 16;
        const float* P = Wp1 + j * 65 + s * 16;
        const float* Q = Wp2 + j * 65 + s * 16;
        const float* F = Wf  + j * 128 + s * 16;
        const float* G = Wg  + j * 128 + s * 16;
        #pragma unroll
        for (int i = 0; i < 8; i++) {
            wa[i]  = pk2(A[2*i], A[2*i+1]);
            wp1[i] = pk2(P[2*i], P[2*i+1]);
            wp2[i] = pk2(Q[2*i], Q[2*i+1]);
            wfh[i] = pk2(F[2*i], F[2*i+1]);
            wgh[i] = pk2(G[2*i], G[2*i+1]);
        }
    }
    // ---- phase-2 weights: slice s of u-half (16 floats = 8 u64) ----
    u64 wfu[8], wgu[8];
    {
        const float* F = Wf + j * 128 + 64 + s * 16;
        const float* G = Wg + j * 128 + 64 + s * 16;
        #pragma unroll
        for (int i = 0; i < 8; i++) {
            wfu[i] = pk2(F[2*i], F[2*i+1]);
            wgu[i] = pk2(G[2*i], G[2*i+1]);
        }
    }

    // ---- finalize constants ----
    float walast = 0.f, w1last = 0.f, w2last = 0.f, ba_r = 0.f, b1_r = 0.f, b2_r = 0.f;
    if (tid < 128) {                        // u-finalize: (e = tid>>6, j)
        walast = Wa [j * 65 + 64]; ba_r = ba [j];
        w1last = Wp1[j * 65 + 64]; b1_r = bp1[j];
        w2last = Wp2[j * 65 + 64]; b2_r = bp2[j];
    }
    float bf_r = 0.f, bg_r = 0.f;
    if (tid >= 128) { bf_r = bf[j]; bg_r = bg[j]; }   // h-finalize: (e=(tid>>6)&1, j)
    float woA0 = 0.f, woB0 = 0.f, woA1 = 0.f, woB1 = 0.f, bo0 = 0.f, bo1 = 0.f;
    if (wid >= 6) {                         // y-output: warps 6,7 -> elem 0,1
        woA0 = Wo[lane];      woB0 = Wo[lane + 32];
        woA1 = Wo[64 + lane]; woB1 = Wo[96 + lane];
        bo0 = bo[0]; bo1 = bo[1];
    }

    // ---- preload x + h0 ----
    {
        const float2* xg0 = (const float2*)x + (size_t)b0 * TB;
        const float2* xg1 = (const float2*)x + (size_t)(b0 + 1) * TB;
        for (int i = tid; i < TB; i += 256) { xb[0][i] = xg0[i]; xb[1][i] = xg1[i]; }
    }
    if (tid < 128) hbuf[tid >> 6][j] = h0[(size_t)(b0 + (tid >> 6)) * 64 + j];
    __syncthreads();

    #pragma unroll 1
    for (int t = 0; t < TB; t++) {
        // ==== phase 1: packed partial dots (5 gates x 2 elems, slice s) ====
        {
            const ulonglong2* h0p = (const ulonglong2*)&hbuf[0][s * 16];
            const ulonglong2* h1p = (const ulonglong2*)&hbuf[1][s * 16];
            u64 aA0 = 0, aP0 = 0, aQ0 = 0, aF0 = 0, aG0 = 0;
            u64 aA1 = 0, aP1 = 0, aQ1 = 0, aF1 = 0, aG1 = 0;
            #pragma unroll
            for (int r = 0; r < 4; r++) {
                ulonglong2 v0 = h0p[r], v1 = h1p[r];
                aA0 = ffma2(wa [2*r], v0.x, aA0); aA0 = ffma2(wa [2*r+1], v0.y, aA0);
                aP0 = ffma2(wp1[2*r], v0.x, aP0); aP0 = ffma2(wp1[2*r+1], v0.y, aP0);
                aQ0 = ffma2(wp2[2*r], v0.x, aQ0); aQ0 = ffma2(wp2[2*r+1], v0.y, aQ0);
                aF0 = ffma2(wfh[2*r], v0.x, aF0); aF0 = ffma2(wfh[2*r+1], v0.y, aF0);
                aG0 = ffma2(wgh[2*r], v0.x, aG0); aG0 = ffma2(wgh[2*r+1], v0.y, aG0);
                aA1 = ffma2(wa [2*r], v1.x, aA1); aA1 = ffma2(wa [2*r+1], v1.y, aA1);
                aP1 = ffma2(wp1[2*r], v1.x, aP1); aP1 = ffma2(wp1[2*r+1], v1.y, aP1);
                aQ1 = ffma2(wp2[2*r], v1.x, aQ1); aQ1 = ffma2(wp2[2*r+1], v1.y, aQ1);
                aF1 = ffma2(wfh[2*r], v1.x, aF1); aF1 = ffma2(wfh[2*r+1], v1.y, aF1);
                aG1 = ffma2(wgh[2*r], v1.x, aG1); aG1 = ffma2(wgh[2*r+1], v1.y, aG1);
            }
            part[0][0][s][j] = aA0;  part[1][0][s][j] = aA1;
            part[0][1][s][j] = aP0;  part[1][1][s][j] = aP1;
            part[0][2][s][j] = aQ0;  part[1][2][s][j] = aQ1;
            part[0][3][s][j] = aF0;  part[1][3][s][j] = aF1;
            part[0][4][s][j] = aG0;  part[1][4][s][j] = aG1;
        }
        __syncthreads();   // #1

        if (tid < 128) {
            // ==== u-finalize (warps 0-3) ====
            const int e = tid >> 6;
            float2 xv = xb[e][t];
            float s2 = fmaf(xv.x, xv.x, xv.y * xv.y);
            float ri = rsqrtf(s2);
            float amp, ct, st;
            if (s2 > 0.f) { amp = s2 * ri; ct = xv.x * ri; st = xv.y * ri; }
            else          { amp = 0.f;     ct = 1.f;       st = 0.f; }
            u64 sa2 = fadd2(fadd2(part[e][0][0][j], part[e][0][1][j]),
                            fadd2(part[e][0][2][j], part[e][0][3][j]));
            u64 sp2 = fadd2(fadd2(part[e][1][0][j], part[e][1][1][j]),
                            fadd2(part[e][1][2][j], part[e][1][3][j]));
            u64 sq2 = fadd2(fadd2(part[e][2][0][j], part[e][2][1][j]),
                            fadd2(part[e][2][2][j], part[e][2][3][j]));
            float av  = tanhfast(fmaf(amp, walast, hadd2(sa2) + ba_r));
            float p1v = tanhfast(fmaf(ct,  w1last, hadd2(sp2) + b1_r));
            float p2v = tanhfast(fmaf(st,  w2last, hadd2(sq2) + b2_r));
            ubuf[e][j] = (av - av * av) * (p1v - p1v * p1v) * (p2v - p2v * p2v);
        } else if (wid >= 6 && t > 0) {
            // ==== y output for step t-1 (warps 6-7, overlapped) ====
            const int e = wid - 6;
            float ha = hbuf[e][lane], hb = hbuf[e][lane + 32];
            float y0 = ha * woA0 + hb * woB0;
            float y1 = ha * woA1 + hb * woB1;
            #pragma unroll
            for (int off = 16; off; off >>= 1) {
                y0 += __shfl_xor_sync(~0u, y0, off);
                y1 += __shfl_xor_sync(~0u, y1, off);
            }
            if (lane == 0)
                ((float2*)out)[(size_t)(b0 + e) * TB + (t - 1)] =
                    make_float2(y0 + bo0, y1 + bo1);
        }
        __syncthreads();   // #2

        // ==== phase 2: f/g u-half packed partial dots (slice s, both elems) ====
        {
            const ulonglong2* u0p = (const ulonglong2*)&ubuf[0][s * 16];
            const ulonglong2* u1p = (const ulonglong2*)&ubuf[1][s * 16];
            u64 cF0 = 0, cG0 = 0, cF1 = 0, cG1 = 0;
            #pragma unroll
            for (int r = 0; r < 4; r++) {
                ulonglong2 v0 = u0p[r], v1 = u1p[r];
                cF0 = ffma2(wfu[2*r], v0.x, cF0); cF0 = ffma2(wfu[2*r+1], v0.y, cF0);
                cG0 = ffma2(wgu[2*r], v0.x, cG0); cG0 = ffma2(wgu[2*r+1], v0.y, cG0);
                cF1 = ffma2(wfu[2*r], v1.x, cF1); cF1 = ffma2(wfu[2*r+1], v1.y, cF1);
                cG1 = ffma2(wgu[2*r], v1.x, cG1); cG1 = ffma2(wgu[2*r+1], v1.y, cG1);
            }
            part[0][0][s][j] = cF0;  part[1][0][s][j] = cF1;
            part[0][1][s][j] = cG0;  part[1][1][s][j] = cG1;
        }
        __syncthreads();   // #3

        if (tid >= 128) {
            // ==== h-finalize (warps 4-7) ====
            const int e = (tid >> 6) & 1;
            u64 sfu = fadd2(fadd2(part[e][0][0][j], part[e][0][1][j]),
                            fadd2(part[e][0][2][j], part[e][0][3][j]));
            u64 sgu = fadd2(fadd2(part[e][1][0][j], part[e][1][1][j]),
                            fadd2(part[e][1][2][j], part[e][1][3][j]));
            u64 sfh = fadd2(fadd2(part[e][3][0][j], part[e][3][1][j]),
                            fadd2(part[e][3][2][j], part[e][3][3][j]));
            u64 sgh = fadd2(fadd2(part[e][4][0][j], part[e][4][1][j]),
                            fadd2(part[e][4][2][j], part[e][4][3][j]));
            float f = sigf(hadd2(fadd2(sfu, sfh)) + bf_r);
            float g = tanhfast(hadd2(fadd2(sgu, sgh)) + bg_r);
            float hold = hbuf[e][j];
            hbuf[e][j] = fmaf(f, hold - g, g);   // f*h + (1-f)*g
        }
        __syncthreads();   // #4
    }

    // ---- epilogue: y for t = TB-1 ----
    if (wid >= 6) {
        const int e = wid - 6;
        float ha = hbuf[e][lane], hb = hbuf[e][lane + 32];
        float y0 = ha * woA0 + hb * woB0;
        float y1 = ha * woA1 + hb * woB1;
        #pragma unroll
        for (int off = 16; off; off >>= 1) {
            y0 += __shfl_xor_sync(~0u, y0, off);
            y1 += __shfl_xor_sync(~0u, y1, off);
        }
        if (lane == 0)
            ((float2*)out)[(size_t)(b0 + e) * TB + (TB - 1)] =
                make_float2(y0 + bo0, y1 + bo1);
    }
}

extern "C" void kernel_launch(void* const* d_in, const int* in_sizes, int n_in,
                              void* d_out, int out_size)
{
    const float* x   = (const float*)d_in[0];
    const float* h0  = (const float*)d_in[1];
    const float* Wa  = (const float*)d_in[2];
    const float* ba  = (const float*)d_in[3];
    const float* Wp1 = (const float*)d_in[4];
    const float* bp1 = (const float*)d_in[5];
    const float* Wp2 = (const float*)d_in[6];
    const float* bp2 = (const float*)d_in[7];
    const float* Wf  = (const float*)d_in[8];
    const float* bf  = (const float*)d_in[9];
    const float* Wg  = (const float*)d_in[10];
    const float* bg  = (const float*)d_in[11];
    const float* Wo  = (const float*)d_in[12];
    const float* bo  = (const float*)d_in[13];
    float* out = (float*)d_out;

    pgjanet_kernel<<<128, 256>>>(x, h0, Wa, ba, Wp1, bp1, Wp2, bp2,
                                 Wf, bf, Wg, bg, Wo, bo, out);
}

// round 8
// speedup vs baseline: 1.1572x; 1.0361x over previous
#include <cuda_runtime.h>

// PGJANET recurrent scan: B=256, T=2048, H=64, O=2.
// 128 blocks x 256 threads, 2 batch elements per block, STAGGERED half-step:
// element 1 runs half a step ahead of element 0. Every dot segment computes
// ph1 (5 gates x 16k) for one elem + ph2 (2 gates x 16k) for the other =
// balanced 112 scalar FMA/thread. Every finalize segment runs u-finalize /
// h-finalize / y-output concurrently on different warps. 4 barriers/step.
// Scalar FFMA only (f32x2 disproven in R2/R5/R7).

#define TB 2048

__device__ __forceinline__ float sigf(float v) {
    return __fdividef(1.f, 1.f + __expf(-v));
}
__device__ __forceinline__ float tanhfast(float v) {
    return fmaf(2.f, sigf(2.f * v), -1.f);
}

__global__ void __launch_bounds__(256, 1)
pgjanet_kernel(const float* __restrict__ x,
               const float* __restrict__ h0,
               const float* __restrict__ Wa,  const float* __restrict__ ba,
               const float* __restrict__ Wp1, const float* __restrict__ bp1,
               const float* __restrict__ Wp2, const float* __restrict__ bp2,
               const float* __restrict__ Wf,  const float* __restrict__ bf,
               const float* __restrict__ Wg,  const float* __restrict__ bg,
               const float* __restrict__ Wo,  const float* __restrict__ bo,
               float* __restrict__ out)
{
    __shared__ __align__(16) float2 xb[2][TB + 1];      // 32.8 KB (padded slot t=TB)
    __shared__ __align__(16) float hbuf[2][64];
    __shared__ __align__(16) float ubuf[2][64];
    __shared__ __align__(16) float partA[2][5][4][64];  // ph1 partials (a,p1,p2,fh,gh)
    __shared__ __align__(16) float partB[2][2][4][64];  // ph2 partials (fu,gu)

    const int tid  = threadIdx.x;
    const int lane = tid & 31;
    const int wid  = tid >> 5;
    const int j    = tid & 63;      // hidden unit (dot phases)
    const int s    = tid >> 6;      // k-slice 0..3
    const int b0   = blockIdx.x * 2;

    // ---- weights in registers (112 floats) ----
    float wa[16], wp1[16], wp2[16], wfh[16], wgh[16], wfu[16], wgu[16];
    {
        const float* A = Wa  + j * 65 + s * 16;
        const float* P = Wp1 + j * 65 + s * 16;
        const float* Q = Wp2 + j * 65 + s * 16;
        const float* F = Wf  + j * 128 + s * 16;
        const float* G = Wg  + j * 128 + s * 16;
        #pragma unroll
        for (int i = 0; i < 16; i++) {
            wa[i]  = A[i];  wp1[i] = P[i];  wp2[i] = Q[i];
            wfh[i] = F[i];  wgh[i] = G[i];
            wfu[i] = F[64 + i]; wgu[i] = G[64 + i];
        }
    }

    // ---- finalize constants: warps 0-1 and 4-5 (both do ufin+hfin, j = tid&63) ----
    const bool finlo = (tid < 64);
    const bool finhi = (tid >= 128 && tid < 192);
    float walast = 0.f, w1last = 0.f, w2last = 0.f, ba_r = 0.f, b1_r = 0.f, b2_r = 0.f;
    float bf_r = 0.f, bg_r = 0.f;
    if (finlo || finhi) {
        walast = Wa [j * 65 + 64]; ba_r = ba [j];
        w1last = Wp1[j * 65 + 64]; b1_r = bp1[j];
        w2last = Wp2[j * 65 + 64]; b2_r = bp2[j];
        bf_r = bf[j]; bg_r = bg[j];
    }
    // ---- y-output constants: warp 2 -> elem 0, warp 6 -> elem 1 ----
    float woA0 = 0.f, woB0 = 0.f, woA1 = 0.f, woB1 = 0.f, bo0 = 0.f, bo1 = 0.f;
    if (wid == 2 || wid == 6) {
        woA0 = Wo[lane];      woB0 = Wo[lane + 32];
        woA1 = Wo[64 + lane]; woB1 = Wo[96 + lane];
        bo0 = bo[0]; bo1 = bo[1];
    }

    // ---- preload x (+ pad slot) + h0 ----
    {
        const float2* xg0 = (const float2*)x + (size_t)b0 * TB;
        const float2* xg1 = (const float2*)x + (size_t)(b0 + 1) * TB;
        for (int i = tid; i < TB; i += 256) { xb[0][i] = xg0[i]; xb[1][i] = xg1[i]; }
        if (tid == 0) { xb[0][TB] = make_float2(0.f, 0.f); xb[1][TB] = make_float2(0.f, 0.f); }
    }
    if (tid < 128) hbuf[tid >> 6][j] = h0[(size_t)(b0 + (tid >> 6)) * 64 + j];
    __syncthreads();

    // ---- phase macros (all threads) ----
#define PH1(E) do {                                                           \
        const float4* hp = (const float4*)&hbuf[E][s * 16];                   \
        float aa = 0.f, ap = 0.f, aq = 0.f, af = 0.f, ag = 0.f;               \
        _Pragma("unroll")                                                     \
        for (int r = 0; r < 4; r++) {                                         \
            float4 v = hp[r];                                                 \
            aa = fmaf(wa [4*r+0], v.x, aa); ap = fmaf(wp1[4*r+0], v.x, ap);   \
            aq = fmaf(wp2[4*r+0], v.x, aq); af = fmaf(wfh[4*r+0], v.x, af);   \
            ag = fmaf(wgh[4*r+0], v.x, ag);                                   \
            aa = fmaf(wa [4*r+1], v.y, aa); ap = fmaf(wp1[4*r+1], v.y, ap);   \
            aq = fmaf(wp2[4*r+1], v.y, aq); af = fmaf(wfh[4*r+1], v.y, af);   \
            ag = fmaf(wgh[4*r+1], v.y, ag);                                   \
            aa = fmaf(wa [4*r+2], v.z, aa); ap = fmaf(wp1[4*r+2], v.z, ap);   \
            aq = fmaf(wp2[4*r+2], v.z, aq); af = fmaf(wfh[4*r+2], v.z, af);   \
            ag = fmaf(wgh[4*r+2], v.z, ag);                                   \
            aa = fmaf(wa [4*r+3], v.w, aa); ap = fmaf(wp1[4*r+3], v.w, ap);   \
            aq = fmaf(wp2[4*r+3], v.w, aq); af = fmaf(wfh[4*r+3], v.w, af);   \
            ag = fmaf(wgh[4*r+3], v.w, ag);                                   \
        }                                                                     \
        partA[E][0][s][j] = aa; partA[E][1][s][j] = ap;                       \
        partA[E][2][s][j] = aq; partA[E][3][s][j] = af;                       \
        partA[E][4][s][j] = ag;                                               \
    } while (0)

#define PH2(E) do {                                                           \
        const float4* up = (const float4*)&ubuf[E][s * 16];                   \
        float cf = 0.f, cg = 0.f;                                             \
        _Pragma("unroll")                                                     \
        for (int r = 0; r < 4; r++) {                                         \
            float4 v = up[r];                                                 \
            cf = fmaf(wfu[4*r+0], v.x, cf); cg = fmaf(wgu[4*r+0], v.x, cg);   \
            cf = fmaf(wfu[4*r+1], v.y, cf); cg = fmaf(wgu[4*r+1], v.y, cg);   \
            cf = fmaf(wfu[4*r+2], v.z, cf); cg = fmaf(wgu[4*r+2], v.z, cg);   \
            cf = fmaf(wfu[4*r+3], v.w, cf); cg = fmaf(wgu[4*r+3], v.w, cg);   \
        }                                                                     \
        partB[E][0][s][j] = cf; partB[E][1][s][j] = cg;                       \
    } while (0)

#define UFIN(E, T) do {                                                       \
        float2 xv = xb[E][T];                                                 \
        float s2 = fmaf(xv.x, xv.x, xv.y * xv.y);                             \
        float ri = rsqrtf(s2);                                                \
        float amp, ct, st;                                                    \
        if (s2 > 0.f) { amp = s2 * ri; ct = xv.x * ri; st = xv.y * ri; }      \
        else          { amp = 0.f;     ct = 1.f;       st = 0.f; }            \
        float sa = partA[E][0][0][j] + partA[E][0][1][j]                      \
                 + partA[E][0][2][j] + partA[E][0][3][j];                     \
        float sp = partA[E][1][0][j] + partA[E][1][1][j]                      \
                 + partA[E][1][2][j] + partA[E][1][3][j];                     \
        float sq = partA[E][2][0][j] + partA[E][2][1][j]                      \
                 + partA[E][2][2][j] + partA[E][2][3][j];                     \
        float av  = tanhfast(fmaf(amp, walast, sa + ba_r));                   \
        float p1v = tanhfast(fmaf(ct,  w1last, sp + b1_r));                   \
        float p2v = tanhfast(fmaf(st,  w2last, sq + b2_r));                   \
        ubuf[E][j] = (av - av * av) * (p1v - p1v * p1v) * (p2v - p2v * p2v);  \
    } while (0)

#define HFIN(E) do {                                                          \
        float sf = partA[E][3][0][j] + partA[E][3][1][j]                      \
                 + partA[E][3][2][j] + partA[E][3][3][j]                      \
                 + partB[E][0][0][j] + partB[E][0][1][j]                      \
                 + partB[E][0][2][j] + partB[E][0][3][j];                     \
        float sg = partA[E][4][0][j] + partA[E][4][1][j]                      \
                 + partA[E][4][2][j] + partA[E][4][3][j]                      \
                 + partB[E][1][0][j] + partB[E][1][1][j]                      \
                 + partB[E][1][2][j] + partB[E][1][3][j];                     \
        float f = sigf(sf + bf_r);                                            \
        float g = tanhfast(sg + bg_r);                                        \
        float hold = hbuf[E][j];                                              \
        hbuf[E][j] = fmaf(f, hold - g, g);                                    \
    } while (0)

#define YOUT(E, T) do {                                                       \
        float ha = hbuf[E][lane], hb = hbuf[E][lane + 32];                    \
        float y0 = ha * woA0 + hb * woB0;                                     \
        float y1 = ha * woA1 + hb * woB1;                                     \
        _Pragma("unroll")                                                     \
        for (int off = 16; off; off >>= 1) {                                  \
            y0 += __shfl_xor_sync(~0u, y0, off);                              \
            y1 += __shfl_xor_sync(~0u, y1, off);                              \
        }                                                                     \
        if (lane == 0)                                                        \
            ((float2*)out)[(size_t)(b0 + (E)) * TB + (T)] =                   \
                make_float2(y0 + bo0, y1 + bo1);                              \
    } while (0)

    // ---- prologue: give elem 1 a half-step head start ----
    PH1(1);
    __syncthreads();
    if (finlo) UFIN(1, 0);
    __syncthreads();

    // ---- main loop: e0 at step t; e1 half a step ahead ----
    #pragma unroll 1
    for (int t = 0; t < TB; t++) {
        // S1: ph1(e0, t) + ph2(e1, t)
        PH1(0);
        PH2(1);
        __syncthreads();

        // S2: ufin(e0,t) | hfin(e1,t) | y(e0, t-1)
        if (finlo)       UFIN(0, t);
        else if (finhi)  HFIN(1);
        else if (wid == 2) { if (t > 0) YOUT(0, t - 1); }
        __syncthreads();

        // S3: ph2(e0, t) + ph1(e1, t+1)
        PH2(0);
        PH1(1);
        __syncthreads();

        // S4: hfin(e0,t) | ufin(e1, t+1) | y(e1, t)
        if (finlo)       HFIN(0);
        else if (finhi)  UFIN(1, t + 1);
        else if (wid == 6) YOUT(1, t);
        __syncthreads();
    }

    // ---- epilogue: y(e0, TB-1) ----
    if (wid == 2) YOUT(0, TB - 1);

#undef PH1
#undef PH2
#undef UFIN
#undef HFIN
#undef YOUT
}

extern "C" void kernel_launch(void* const* d_in, const int* in_sizes, int n_in,
                              void* d_out, int out_size)
{
    const float* x   = (const float*)d_in[0];
    const float* h0  = (const float*)d_in[1];
    const float* Wa  = (const float*)d_in[2];
    const float* ba  = (const float*)d_in[3];
    const float* Wp1 = (const float*)d_in[4];
    const float* bp1 = (const float*)d_in[5];
    const float* Wp2 = (const float*)d_in[6];
    const float* bp2 = (const float*)d_in[7];
    const float* Wf  = (const float*)d_in[8];
    const float* bf  = (const float*)d_in[9];
    const float* Wg  = (const float*)d_in[10];
    const float* bg  = (const float*)d_in[11];
    const float* Wo  = (const float*)d_in[12];
    const float* bo  = (const float*)d_in[13];
    float* out = (float*)d_out;

    pgjanet_kernel<<<128, 256>>>(x, h0, Wa, ba, Wp1, bp1, Wp2, bp2,
                                 Wf, bf, Wg, bg, Wo, bo, out);
}